// round 14
// baseline (speedup 1.0000x reference)
#include <cuda_runtime.h>
#include <cuda_fp16.h>
#include <cstdint>

#define N_NODES 50000
#define N_EDGES 800000
#define N_FEAT  500
#define N_HID   256
#define DCAT    512   // fused hidden width (2 branches x 256)
#define N_CLASS 10
#define MPAD    50048 // 391 * 128
#define KPAD    512

// ---------------- device scratch ----------------------------------------------
__device__ int   g_is64;
__device__ int   g_counts[N_NODES];
__device__ int   g_row_start[N_NODES + 1];
__device__ int   g_cursor[N_NODES];
__device__ int   g_blockSums[256];
__device__ int   g_blockOffs[256];
__device__ int   g_col[N_EDGES];
__device__ float g_w[N_EDGES];
__device__ __align__(16) __half g_xh[(size_t)MPAD * KPAD];   // fp16(x)
__device__ __align__(16) __half g_whT[DCAT * KPAD];          // [n][k] fp16(w)
__device__ float g_bcat[DCAT];
__device__ __align__(16) __half g_yh[(size_t)MPAD * DCAT];   // y in fp16
__device__ __align__(16) __half g_gh[(size_t)N_NODES * DCAT];// relu(spmm(y)) fp16
__device__ __half g_zh[(size_t)N_NODES * 20];                // z in fp16

#define CP_ASYNC16(dst, src) \
    asm volatile("cp.async.cg.shared.global [%0], [%1], 16;" :: "r"(dst), "l"(src))
#define CP_COMMIT() asm volatile("cp.async.commit_group;" ::: "memory")
#define CP_WAIT0()  asm volatile("cp.async.wait_group 0;" ::: "memory")

__device__ __forceinline__ uint32_t smem_u32(const void* p) {
    uint32_t a;
    asm("{ .reg .u64 t; cvta.to.shared.u64 t, %1; cvt.u32.u64 %0, t; }" : "=r"(a) : "l"(p));
    return a;
}

// ---------------- dtype detect ------------------------------------------------
__global__ void k_detect(const int* __restrict__ ei32) {
    if (threadIdx.x == 0) {
        int odd_nonzero = 0;
        for (int i = 0; i < 64; i++) odd_nonzero |= ei32[2 * i + 1];
        g_is64 = (odd_nonzero == 0) ? 1 : 0;
    }
}
__device__ __forceinline__ int edge_row(const int* ei32, int e, int is64) {
    return is64 ? ei32[2 * e] : ei32[e];
}
__device__ __forceinline__ int edge_col(const int* ei32, int e, int is64) {
    return is64 ? ei32[2 * (N_EDGES + e)] : ei32[N_EDGES + e];
}

// ---------------- CSR build ---------------------------------------------------
__global__ void k_zero() {
    int i = blockIdx.x * blockDim.x + threadIdx.x;
    if (i < N_NODES) { g_counts[i] = 0; g_cursor[i] = 0; }
}
__global__ void k_hist(const int* __restrict__ ei32) {
    int e = blockIdx.x * blockDim.x + threadIdx.x;
    if (e < N_EDGES) {
        int r = edge_row(ei32, e, g_is64);
        if ((unsigned)r < N_NODES) atomicAdd(&g_counts[r], 1);
    }
}
__global__ void k_scan1() {
    __shared__ int sm[256];
    int i = blockIdx.x * 256 + threadIdx.x;
    sm[threadIdx.x] = (i < N_NODES) ? g_counts[i] : 0;
    __syncthreads();
    for (int off = 128; off; off >>= 1) {
        if (threadIdx.x < off) sm[threadIdx.x] += sm[threadIdx.x + off];
        __syncthreads();
    }
    if (threadIdx.x == 0) g_blockSums[blockIdx.x] = sm[0];
}
__global__ void k_scan2(int nblocks) {
    __shared__ int sm[256];
    int v = (threadIdx.x < nblocks) ? g_blockSums[threadIdx.x] : 0;
    sm[threadIdx.x] = v;
    __syncthreads();
    for (int off = 1; off < 256; off <<= 1) {
        int t = (threadIdx.x >= off) ? sm[threadIdx.x - off] : 0;
        __syncthreads();
        sm[threadIdx.x] += t;
        __syncthreads();
    }
    if (threadIdx.x < nblocks) g_blockOffs[threadIdx.x] = sm[threadIdx.x] - v;
    if (threadIdx.x == 255) g_row_start[N_NODES] = sm[255];
}
__global__ void k_scan3() {
    __shared__ int sm[256];
    int i = blockIdx.x * 256 + threadIdx.x;
    int v = (i < N_NODES) ? g_counts[i] : 0;
    sm[threadIdx.x] = v;
    __syncthreads();
    for (int off = 1; off < 256; off <<= 1) {
        int t = (threadIdx.x >= off) ? sm[threadIdx.x - off] : 0;
        __syncthreads();
        sm[threadIdx.x] += t;
        __syncthreads();
    }
    if (i < N_NODES) g_row_start[i] = g_blockOffs[blockIdx.x] + sm[threadIdx.x] - v;
}
__global__ void k_scatter(const int* __restrict__ ei32, const float* __restrict__ ew) {
    int e = blockIdx.x * blockDim.x + threadIdx.x;
    if (e < N_EDGES) {
        int is64 = g_is64;
        int r = edge_row(ei32, e, is64);
        int c = edge_col(ei32, e, is64);
        if ((unsigned)r < N_NODES && (unsigned)c < N_NODES) {
            int p = g_row_start[r] + atomicAdd(&g_cursor[r], 1);
            g_col[p] = c;
            g_w[p]   = ew[e];
        }
    }
}

// ---------------- prep: x -> fp16, w -> fp16 -----------------------------------
__global__ void k_prep_x(const float* __restrict__ x) {
    int t  = blockIdx.x * 256 + threadIdx.x;
    int r  = t >> 7;
    int c0 = (t & 127) * 4;
    if (r >= MPAD) return;
    float4 v = make_float4(0.f, 0.f, 0.f, 0.f);
    if (r < N_NODES && c0 < N_FEAT)
        v = *(const float4*)(x + (size_t)r * N_FEAT + c0);
    __half h[4];
    h[0] = __float2half_rn(v.x); h[1] = __float2half_rn(v.y);
    h[2] = __float2half_rn(v.z); h[3] = __float2half_rn(v.w);
    *(uint2*)(g_xh + (size_t)r * KPAD + c0) = *(uint2*)h;
}
__global__ void k_prep_w(const float* __restrict__ W1a, const float* __restrict__ b1a,
                         const float* __restrict__ W1b, const float* __restrict__ b1b) {
    int t = blockIdx.x * 256 + threadIdx.x;
    if (t >= DCAT * KPAD) return;
    int n = t >> 9, k = t & 511;
    float v = 0.f;
    if (k < N_FEAT)
        v = (n < N_HID) ? W1a[k * N_HID + n] : W1b[k * N_HID + (n - N_HID)];
    g_whT[n * KPAD + k] = __float2half_rn(v);
    if (t < DCAT) g_bcat[t] = (t < N_HID) ? b1a[t] : b1b[t - N_HID];
}

// ---------------- GEMM1 (fp16: y = xh*wh), cp.async ---------------------------
#define BM 128
#define BN 128
#define BK 16
#define PITCH 24

__device__ __forceinline__ void mma16816(float* c, const unsigned* a, const unsigned* b) {
    asm volatile(
        "mma.sync.aligned.m16n8k16.row.col.f32.f16.f16.f32 "
        "{%0,%1,%2,%3}, {%4,%5,%6,%7}, {%8,%9}, {%0,%1,%2,%3};\n"
        : "+f"(c[0]), "+f"(c[1]), "+f"(c[2]), "+f"(c[3])
        : "r"(a[0]), "r"(a[1]), "r"(a[2]), "r"(a[3]), "r"(b[0]), "r"(b[1]));
}

__global__ void __launch_bounds__(256, 2) k_gemm1_mma() {
    __shared__ __align__(16) __half sAh[2][BM * PITCH];
    __shared__ __align__(16) __half sBh[2][BN * PITCH];

    const int tid  = threadIdx.x;
    const int bm   = blockIdx.y * BM;
    const int bn   = blockIdx.x * BN;
    const int wid  = tid >> 5, lane = tid & 31;
    const int wm   = wid & 1, wn = wid >> 1;
    const int mw   = wm * 64, nw = wn * 32;
    const int gid  = lane >> 2;
    const int tk4  = lane & 3;

    const int lr = tid >> 1;
    const int lk = (tid & 1) * 8;
    const size_t aoff = (size_t)(bm + lr) * KPAD + lk;
    const size_t boff = (size_t)(bn + lr) * KPAD + lk;
    const uint32_t sAh0 = smem_u32(&sAh[0][0]);
    const uint32_t sBh0 = smem_u32(&sBh[0][0]);
    const uint32_t soffB = (lr * PITCH + lk) * 2;
    const uint32_t stageB = BM * PITCH * 2;

    float acc[16][4];
#pragma unroll
    for (int i = 0; i < 16; i++)
#pragma unroll
        for (int j = 0; j < 4; j++) acc[i][j] = 0.f;

    CP_ASYNC16(sAh0 + soffB, g_xh + aoff);
    CP_ASYNC16(sBh0 + soffB, g_whT + boff);
    CP_COMMIT();
    CP_WAIT0();
    __syncthreads();

    const int NSTAGE = KPAD / BK;  // 32
    for (int s = 0; s < NSTAGE; s++) {
        const int cur = s & 1, nxt = cur ^ 1;
        if (s + 1 < NSTAGE) {
            int k0 = (s + 1) * BK;
            uint32_t so = nxt * stageB + soffB;
            CP_ASYNC16(sAh0 + so, g_xh + aoff + k0);
            CP_ASYNC16(sBh0 + so, g_whT + boff + k0);
            CP_COMMIT();
        }

        unsigned Ah[4][4], Bh[4][2];
#pragma unroll
        for (int ni = 0; ni < 4; ni++) {
            int n = nw + ni * 8 + gid;
            Bh[ni][0] = *(const unsigned*)&sBh[cur][n * PITCH + tk4 * 2];
            Bh[ni][1] = *(const unsigned*)&sBh[cur][n * PITCH + tk4 * 2 + 8];
        }
#pragma unroll
        for (int mi = 0; mi < 4; mi++) {
            int m = mw + mi * 16 + gid;
            Ah[mi][0] = *(const unsigned*)&sAh[cur][m * PITCH + tk4 * 2];
            Ah[mi][1] = *(const unsigned*)&sAh[cur][(m + 8) * PITCH + tk4 * 2];
            Ah[mi][2] = *(const unsigned*)&sAh[cur][m * PITCH + tk4 * 2 + 8];
            Ah[mi][3] = *(const unsigned*)&sAh[cur][(m + 8) * PITCH + tk4 * 2 + 8];
        }
#pragma unroll
        for (int mi = 0; mi < 4; mi++)
#pragma unroll
            for (int ni = 0; ni < 4; ni++)
                mma16816(acc[mi * 4 + ni], Ah[mi], Bh[ni]);

        if (s + 1 < NSTAGE) CP_WAIT0();
        __syncthreads();
    }

    // epilogue: bias add in fp32, store fp16
#pragma unroll
    for (int mi = 0; mi < 4; mi++) {
#pragma unroll
        for (int ni = 0; ni < 4; ni++) {
            int r = bm + mw + mi * 16 + gid;
            int c = bn + nw + ni * 8 + tk4 * 2;
            float b0 = g_bcat[c], b1 = g_bcat[c + 1];
            float* acc4 = acc[mi * 4 + ni];
            __half2 h0 = __floats2half2_rn(acc4[0] + b0, acc4[1] + b1);
            __half2 h1 = __floats2half2_rn(acc4[2] + b0, acc4[3] + b1);
            *reinterpret_cast<__half2*>(&g_yh[(size_t)r * DCAT + c]) = h0;
            *reinterpret_cast<__half2*>(&g_yh[(size_t)(r + 8) * DCAT + c]) = h1;
        }
    }
}

// ---------------- SpMM1: gh[row] = relu( sum_e w * yh[col] ), D=512 -----------
// 4x unrolled edge loop: all gathers issued before consumption (MLP >= 4)
__global__ void __launch_bounds__(128) k_spmm1() {
    int row = blockIdx.x;
    int s = g_row_start[row], t = g_row_start[row + 1];
    const __half* yb = g_yh + threadIdx.x * 4;
    float ax = 0.f, ay = 0.f, az = 0.f, aw = 0.f;
    int e = s;
    for (; e + 4 <= t; e += 4) {
        int c0 = __ldg(&g_col[e]),     c1 = __ldg(&g_col[e + 1]);
        int c2 = __ldg(&g_col[e + 2]), c3 = __ldg(&g_col[e + 3]);
        float w0 = __ldg(&g_w[e]),     w1 = __ldg(&g_w[e + 1]);
        float w2 = __ldg(&g_w[e + 2]), w3 = __ldg(&g_w[e + 3]);
        uint2 v0 = *(const uint2*)(yb + (size_t)c0 * DCAT);
        uint2 v1 = *(const uint2*)(yb + (size_t)c1 * DCAT);
        uint2 v2 = *(const uint2*)(yb + (size_t)c2 * DCAT);
        uint2 v3 = *(const uint2*)(yb + (size_t)c3 * DCAT);
        float2 a0 = __half22float2(*reinterpret_cast<__half2*>(&v0.x));
        float2 b0 = __half22float2(*reinterpret_cast<__half2*>(&v0.y));
        float2 a1 = __half22float2(*reinterpret_cast<__half2*>(&v1.x));
        float2 b1 = __half22float2(*reinterpret_cast<__half2*>(&v1.y));
        float2 a2 = __half22float2(*reinterpret_cast<__half2*>(&v2.x));
        float2 b2 = __half22float2(*reinterpret_cast<__half2*>(&v2.y));
        float2 a3 = __half22float2(*reinterpret_cast<__half2*>(&v3.x));
        float2 b3 = __half22float2(*reinterpret_cast<__half2*>(&v3.y));
        ax += w0 * a0.x + w1 * a1.x + w2 * a2.x + w3 * a3.x;
        ay += w0 * a0.y + w1 * a1.y + w2 * a2.y + w3 * a3.y;
        az += w0 * b0.x + w1 * b1.x + w2 * b2.x + w3 * b3.x;
        aw += w0 * b0.y + w1 * b1.y + w2 * b2.y + w3 * b3.y;
    }
    for (; e < t; e++) {
        int   c = __ldg(&g_col[e]);
        float w = __ldg(&g_w[e]);
        uint2 v = *(const uint2*)(yb + (size_t)c * DCAT);
        float2 f0 = __half22float2(*reinterpret_cast<__half2*>(&v.x));
        float2 f1 = __half22float2(*reinterpret_cast<__half2*>(&v.y));
        ax += w * f0.x; ay += w * f0.y; az += w * f1.x; aw += w * f1.y;
    }
    __half2 o0 = __floats2half2_rn(fmaxf(ax, 0.f), fmaxf(ay, 0.f));
    __half2 o1 = __floats2half2_rn(fmaxf(az, 0.f), fmaxf(aw, 0.f));
    uint2 o; o.x = *reinterpret_cast<uint32_t*>(&o0); o.y = *reinterpret_cast<uint32_t*>(&o1);
    *(uint2*)(g_gh + (size_t)row * DCAT + threadIdx.x * 4) = o;
}

// ---------------- GEMM2 (fp16 g input, fp16 z output) --------------------------
__global__ void __launch_bounds__(256) k_gemm2(
    const float* __restrict__ W2a, const float* __restrict__ b2a,
    const float* __restrict__ W2b, const float* __restrict__ b2b)
{
    __shared__ float sW[DCAT * 10];
    for (int i = threadIdx.x; i < DCAT * 10; i += blockDim.x) {
        int d = i / 10, c = i % 10;
        sW[i] = (d < N_HID) ? W2a[d * 10 + c] : W2b[(d - N_HID) * 10 + c];
    }
    __syncthreads();

    int lane   = threadIdx.x & 31;
    int warp   = (blockIdx.x * blockDim.x + threadIdx.x) >> 5;
    int nwarps = (gridDim.x * blockDim.x) >> 5;

    for (int row = warp; row < N_NODES; row += nwarps) {
        float acc[20];
#pragma unroll
        for (int c = 0; c < 20; c++) acc[c] = 0.f;
        const __half* grow = &g_gh[(size_t)row * DCAT];
#pragma unroll
        for (int k = 0; k < 8; k++) {
            int d0 = 64 * k + 2 * lane;
            __half2 hv = *reinterpret_cast<const __half2*>(grow + d0);
            float2 f = __half22float2(hv);
            const float* w0 = &sW[d0 * 10];
            const float* w1 = &sW[(d0 + 1) * 10];
            float* ap = (k < 4) ? acc : acc + 10;
#pragma unroll
            for (int c = 0; c < 10; c++) ap[c] += f.x * w0[c] + f.y * w1[c];
        }
#pragma unroll
        for (int c = 0; c < 20; c++) {
            float v = acc[c];
            v += __shfl_xor_sync(0xffffffffu, v, 16);
            v += __shfl_xor_sync(0xffffffffu, v, 8);
            v += __shfl_xor_sync(0xffffffffu, v, 4);
            v += __shfl_xor_sync(0xffffffffu, v, 2);
            v += __shfl_xor_sync(0xffffffffu, v, 1);
            acc[c] = v;
        }
        if (lane == 0) {
#pragma unroll
            for (int c = 0; c < 10; c++)
                g_zh[(size_t)row * 20 + c] = __float2half_rn(acc[c] + b2a[c]);
#pragma unroll
            for (int c = 0; c < 10; c++)
                g_zh[(size_t)row * 20 + 10 + c] = __float2half_rn(acc[10 + c] + b2b[c]);
        }
    }
}

// ---------------- SpMM2: 320 threads = 16 rows x 20 lanes, 4x unroll ----------
__global__ void __launch_bounds__(320) k_spmm2(float* __restrict__ out) {
    int t    = threadIdx.x;
    int row  = blockIdx.x * 16 + t / 20;
    int c20  = t % 20;
    if (row >= N_NODES) return;
    int s = g_row_start[row], tend = g_row_start[row + 1];
    float acc = 0.f;
    int e = s;
    for (; e + 4 <= tend; e += 4) {
        int c0 = __ldg(&g_col[e]),     c1 = __ldg(&g_col[e + 1]);
        int c2 = __ldg(&g_col[e + 2]), c3 = __ldg(&g_col[e + 3]);
        float w0 = __ldg(&g_w[e]),     w1 = __ldg(&g_w[e + 1]);
        float w2 = __ldg(&g_w[e + 2]), w3 = __ldg(&g_w[e + 3]);
        __half z0 = g_zh[(size_t)c0 * 20 + c20];
        __half z1 = g_zh[(size_t)c1 * 20 + c20];
        __half z2 = g_zh[(size_t)c2 * 20 + c20];
        __half z3 = g_zh[(size_t)c3 * 20 + c20];
        acc += w0 * __half2float(z0) + w1 * __half2float(z1)
             + w2 * __half2float(z2) + w3 * __half2float(z3);
    }
    for (; e < tend; e++) {
        int   c = __ldg(&g_col[e]);
        float w = __ldg(&g_w[e]);
        acc += w * __half2float(g_zh[(size_t)c * 20 + c20]);
    }
    int br = c20 / 10, cc = c20 % 10;
    out[(size_t)br * (N_NODES * N_CLASS) + (size_t)row * N_CLASS + cc] = acc;
}

// ---------------- launch ------------------------------------------------------
extern "C" void kernel_launch(void* const* d_in, const int* in_sizes, int n_in,
                              void* d_out, int out_size)
{
    const float* x   = (const float*)d_in[0];
    const int*   ei  = (const int*)d_in[1];
    const float* ew  = (const float*)d_in[2];
    const float* W1a = (const float*)d_in[3];
    const float* b1a = (const float*)d_in[4];
    const float* W2a = (const float*)d_in[5];
    const float* b2a = (const float*)d_in[6];
    const float* W1b = (const float*)d_in[7];
    const float* b1b = (const float*)d_in[8];
    const float* W2b = (const float*)d_in[9];
    const float* b2b = (const float*)d_in[10];
    float* out = (float*)d_out;

    const int SCAN_BLOCKS = (N_NODES + 255) / 256;  // 196

    k_detect<<<1, 32>>>(ei);
    k_zero<<<(N_NODES + 255) / 256, 256>>>();
    k_hist<<<(N_EDGES + 255) / 256, 256>>>(ei);
    k_scan1<<<SCAN_BLOCKS, 256>>>();
    k_scan2<<<1, 256>>>(SCAN_BLOCKS);
    k_scan3<<<SCAN_BLOCKS, 256>>>();
    k_scatter<<<(N_EDGES + 255) / 256, 256>>>(ei, ew);
    k_prep_x<<<(MPAD * 128 + 255) / 256, 256>>>(x);
    k_prep_w<<<(DCAT * KPAD + 255) / 256, 256>>>(W1a, b1a, W1b, b1b);
    k_gemm1_mma<<<dim3(DCAT / BN, MPAD / BM), 256>>>();
    k_spmm1<<<N_NODES, 128>>>();
    k_gemm2<<<782, 256>>>(W2a, b2a, W2b, b2b);
    k_spmm2<<<(N_NODES + 15) / 16, 320>>>(out);
}

// round 15
// speedup vs baseline: 1.0438x; 1.0438x over previous
#include <cuda_runtime.h>
#include <cuda_fp16.h>
#include <cstdint>

#define N_NODES 50000
#define N_EDGES 800000
#define N_FEAT  500
#define N_HID   256
#define DCAT    512   // fused hidden width (2 branches x 256)
#define N_CLASS 10
#define MPAD    50048 // 391 * 128
#define KPAD    512

// ---------------- device scratch ----------------------------------------------
__device__ int   g_is64;
__device__ int   g_counts[N_NODES];
__device__ int   g_row_start[N_NODES + 1];
__device__ int   g_cursor[N_NODES];
__device__ int   g_blockSums[256];
__device__ int   g_blockOffs[256];
__device__ int   g_col[N_EDGES];
__device__ float g_w[N_EDGES];
__device__ __align__(16) __half g_xh[(size_t)MPAD * KPAD];   // fp16(x)
__device__ __align__(16) __half g_whT[DCAT * KPAD];          // [n][k] fp16(w)
__device__ float g_bcat[DCAT];
__device__ __align__(16) __half g_yh[(size_t)MPAD * DCAT];   // y in fp16
__device__ __align__(16) __half g_gh[(size_t)N_NODES * DCAT];// relu(spmm(y)) fp16
__device__ __half g_zh[(size_t)N_NODES * 20];                // z in fp16

#define CP_ASYNC16(dst, src) \
    asm volatile("cp.async.cg.shared.global [%0], [%1], 16;" :: "r"(dst), "l"(src))
#define CP_COMMIT() asm volatile("cp.async.commit_group;" ::: "memory")
#define CP_WAIT0()  asm volatile("cp.async.wait_group 0;" ::: "memory")

__device__ __forceinline__ uint32_t smem_u32(const void* p) {
    uint32_t a;
    asm("{ .reg .u64 t; cvta.to.shared.u64 t, %1; cvt.u32.u64 %0, t; }" : "=r"(a) : "l"(p));
    return a;
}

// ---------------- dtype detect ------------------------------------------------
__global__ void k_detect(const int* __restrict__ ei32) {
    if (threadIdx.x == 0) {
        int odd_nonzero = 0;
        for (int i = 0; i < 64; i++) odd_nonzero |= ei32[2 * i + 1];
        g_is64 = (odd_nonzero == 0) ? 1 : 0;
    }
}
__device__ __forceinline__ int edge_row(const int* ei32, int e, int is64) {
    return is64 ? ei32[2 * e] : ei32[e];
}
__device__ __forceinline__ int edge_col(const int* ei32, int e, int is64) {
    return is64 ? ei32[2 * (N_EDGES + e)] : ei32[N_EDGES + e];
}

// ---------------- CSR build ---------------------------------------------------
__global__ void k_zero() {
    int i = blockIdx.x * blockDim.x + threadIdx.x;
    if (i < N_NODES) { g_counts[i] = 0; g_cursor[i] = 0; }
}
__global__ void k_hist(const int* __restrict__ ei32) {
    int e = blockIdx.x * blockDim.x + threadIdx.x;
    if (e < N_EDGES) {
        int r = edge_row(ei32, e, g_is64);
        if ((unsigned)r < N_NODES) atomicAdd(&g_counts[r], 1);
    }
}
__global__ void k_scan1() {
    __shared__ int sm[256];
    int i = blockIdx.x * 256 + threadIdx.x;
    sm[threadIdx.x] = (i < N_NODES) ? g_counts[i] : 0;
    __syncthreads();
    for (int off = 128; off; off >>= 1) {
        if (threadIdx.x < off) sm[threadIdx.x] += sm[threadIdx.x + off];
        __syncthreads();
    }
    if (threadIdx.x == 0) g_blockSums[blockIdx.x] = sm[0];
}
__global__ void k_scan2(int nblocks) {
    __shared__ int sm[256];
    int v = (threadIdx.x < nblocks) ? g_blockSums[threadIdx.x] : 0;
    sm[threadIdx.x] = v;
    __syncthreads();
    for (int off = 1; off < 256; off <<= 1) {
        int t = (threadIdx.x >= off) ? sm[threadIdx.x - off] : 0;
        __syncthreads();
        sm[threadIdx.x] += t;
        __syncthreads();
    }
    if (threadIdx.x < nblocks) g_blockOffs[threadIdx.x] = sm[threadIdx.x] - v;
    if (threadIdx.x == 255) g_row_start[N_NODES] = sm[255];
}
__global__ void k_scan3() {
    __shared__ int sm[256];
    int i = blockIdx.x * 256 + threadIdx.x;
    int v = (i < N_NODES) ? g_counts[i] : 0;
    sm[threadIdx.x] = v;
    __syncthreads();
    for (int off = 1; off < 256; off <<= 1) {
        int t = (threadIdx.x >= off) ? sm[threadIdx.x - off] : 0;
        __syncthreads();
        sm[threadIdx.x] += t;
        __syncthreads();
    }
    if (i < N_NODES) g_row_start[i] = g_blockOffs[blockIdx.x] + sm[threadIdx.x] - v;
}
__global__ void k_scatter(const int* __restrict__ ei32, const float* __restrict__ ew) {
    int e = blockIdx.x * blockDim.x + threadIdx.x;
    if (e < N_EDGES) {
        int is64 = g_is64;
        int r = edge_row(ei32, e, is64);
        int c = edge_col(ei32, e, is64);
        if ((unsigned)r < N_NODES && (unsigned)c < N_NODES) {
            int p = g_row_start[r] + atomicAdd(&g_cursor[r], 1);
            g_col[p] = c;
            g_w[p]   = ew[e];
        }
    }
}

// ---------------- prep: x -> fp16, w -> fp16 -----------------------------------
__global__ void k_prep_x(const float* __restrict__ x) {
    int t  = blockIdx.x * 256 + threadIdx.x;
    int r  = t >> 7;
    int c0 = (t & 127) * 4;
    if (r >= MPAD) return;
    float4 v = make_float4(0.f, 0.f, 0.f, 0.f);
    if (r < N_NODES && c0 < N_FEAT)
        v = *(const float4*)(x + (size_t)r * N_FEAT + c0);
    __half h[4];
    h[0] = __float2half_rn(v.x); h[1] = __float2half_rn(v.y);
    h[2] = __float2half_rn(v.z); h[3] = __float2half_rn(v.w);
    *(uint2*)(g_xh + (size_t)r * KPAD + c0) = *(uint2*)h;
}
__global__ void k_prep_w(const float* __restrict__ W1a, const float* __restrict__ b1a,
                         const float* __restrict__ W1b, const float* __restrict__ b1b) {
    int t = blockIdx.x * 256 + threadIdx.x;
    if (t >= DCAT * KPAD) return;
    int n = t >> 9, k = t & 511;
    float v = 0.f;
    if (k < N_FEAT)
        v = (n < N_HID) ? W1a[k * N_HID + n] : W1b[k * N_HID + (n - N_HID)];
    g_whT[n * KPAD + k] = __float2half_rn(v);
    if (t < DCAT) g_bcat[t] = (t < N_HID) ? b1a[t] : b1b[t - N_HID];
}

// ---------------- GEMM1 (fp16: y = xh*wh), cp.async ---------------------------
#define BM 128
#define BN 128
#define BK 16
#define PITCH 24

__device__ __forceinline__ void mma16816(float* c, const unsigned* a, const unsigned* b) {
    asm volatile(
        "mma.sync.aligned.m16n8k16.row.col.f32.f16.f16.f32 "
        "{%0,%1,%2,%3}, {%4,%5,%6,%7}, {%8,%9}, {%0,%1,%2,%3};\n"
        : "+f"(c[0]), "+f"(c[1]), "+f"(c[2]), "+f"(c[3])
        : "r"(a[0]), "r"(a[1]), "r"(a[2]), "r"(a[3]), "r"(b[0]), "r"(b[1]));
}

__global__ void __launch_bounds__(256, 2) k_gemm1_mma() {
    __shared__ __align__(16) __half sAh[2][BM * PITCH];
    __shared__ __align__(16) __half sBh[2][BN * PITCH];

    const int tid  = threadIdx.x;
    const int bm   = blockIdx.y * BM;
    const int bn   = blockIdx.x * BN;
    const int wid  = tid >> 5, lane = tid & 31;
    const int wm   = wid & 1, wn = wid >> 1;
    const int mw   = wm * 64, nw = wn * 32;
    const int gid  = lane >> 2;
    const int tk4  = lane & 3;

    const int lr = tid >> 1;
    const int lk = (tid & 1) * 8;
    const size_t aoff = (size_t)(bm + lr) * KPAD + lk;
    const size_t boff = (size_t)(bn + lr) * KPAD + lk;
    const uint32_t sAh0 = smem_u32(&sAh[0][0]);
    const uint32_t sBh0 = smem_u32(&sBh[0][0]);
    const uint32_t soffB = (lr * PITCH + lk) * 2;
    const uint32_t stageB = BM * PITCH * 2;

    float acc[16][4];
#pragma unroll
    for (int i = 0; i < 16; i++)
#pragma unroll
        for (int j = 0; j < 4; j++) acc[i][j] = 0.f;

    CP_ASYNC16(sAh0 + soffB, g_xh + aoff);
    CP_ASYNC16(sBh0 + soffB, g_whT + boff);
    CP_COMMIT();
    CP_WAIT0();
    __syncthreads();

    const int NSTAGE = KPAD / BK;  // 32
    for (int s = 0; s < NSTAGE; s++) {
        const int cur = s & 1, nxt = cur ^ 1;
        if (s + 1 < NSTAGE) {
            int k0 = (s + 1) * BK;
            uint32_t so = nxt * stageB + soffB;
            CP_ASYNC16(sAh0 + so, g_xh + aoff + k0);
            CP_ASYNC16(sBh0 + so, g_whT + boff + k0);
            CP_COMMIT();
        }

        unsigned Ah[4][4], Bh[4][2];
#pragma unroll
        for (int ni = 0; ni < 4; ni++) {
            int n = nw + ni * 8 + gid;
            Bh[ni][0] = *(const unsigned*)&sBh[cur][n * PITCH + tk4 * 2];
            Bh[ni][1] = *(const unsigned*)&sBh[cur][n * PITCH + tk4 * 2 + 8];
        }
#pragma unroll
        for (int mi = 0; mi < 4; mi++) {
            int m = mw + mi * 16 + gid;
            Ah[mi][0] = *(const unsigned*)&sAh[cur][m * PITCH + tk4 * 2];
            Ah[mi][1] = *(const unsigned*)&sAh[cur][(m + 8) * PITCH + tk4 * 2];
            Ah[mi][2] = *(const unsigned*)&sAh[cur][m * PITCH + tk4 * 2 + 8];
            Ah[mi][3] = *(const unsigned*)&sAh[cur][(m + 8) * PITCH + tk4 * 2 + 8];
        }
#pragma unroll
        for (int mi = 0; mi < 4; mi++)
#pragma unroll
            for (int ni = 0; ni < 4; ni++)
                mma16816(acc[mi * 4 + ni], Ah[mi], Bh[ni]);

        if (s + 1 < NSTAGE) CP_WAIT0();
        __syncthreads();
    }

#pragma unroll
    for (int mi = 0; mi < 4; mi++) {
#pragma unroll
        for (int ni = 0; ni < 4; ni++) {
            int r = bm + mw + mi * 16 + gid;
            int c = bn + nw + ni * 8 + tk4 * 2;
            float b0 = g_bcat[c], b1 = g_bcat[c + 1];
            float* acc4 = acc[mi * 4 + ni];
            __half2 h0 = __floats2half2_rn(acc4[0] + b0, acc4[1] + b1);
            __half2 h1 = __floats2half2_rn(acc4[2] + b0, acc4[3] + b1);
            *reinterpret_cast<__half2*>(&g_yh[(size_t)r * DCAT + c]) = h0;
            *reinterpret_cast<__half2*>(&g_yh[(size_t)(r + 8) * DCAT + c]) = h1;
        }
    }
}

// ---------------- SpMM1: gh[row] = relu( sum_e w * yh[col] ), D=512 -----------
__global__ void __launch_bounds__(128) k_spmm1() {
    int row = blockIdx.x;
    int s = g_row_start[row], t = g_row_start[row + 1];
    const __half* yb = g_yh + threadIdx.x * 4;
    float ax = 0.f, ay = 0.f, az = 0.f, aw = 0.f;
    int e = s;
    for (; e + 4 <= t; e += 4) {
        int c0 = __ldg(&g_col[e]),     c1 = __ldg(&g_col[e + 1]);
        int c2 = __ldg(&g_col[e + 2]), c3 = __ldg(&g_col[e + 3]);
        float w0 = __ldg(&g_w[e]),     w1 = __ldg(&g_w[e + 1]);
        float w2 = __ldg(&g_w[e + 2]), w3 = __ldg(&g_w[e + 3]);
        uint2 v0 = *(const uint2*)(yb + (size_t)c0 * DCAT);
        uint2 v1 = *(const uint2*)(yb + (size_t)c1 * DCAT);
        uint2 v2 = *(const uint2*)(yb + (size_t)c2 * DCAT);
        uint2 v3 = *(const uint2*)(yb + (size_t)c3 * DCAT);
        float2 a0 = __half22float2(*reinterpret_cast<__half2*>(&v0.x));
        float2 b0 = __half22float2(*reinterpret_cast<__half2*>(&v0.y));
        float2 a1 = __half22float2(*reinterpret_cast<__half2*>(&v1.x));
        float2 b1 = __half22float2(*reinterpret_cast<__half2*>(&v1.y));
        float2 a2 = __half22float2(*reinterpret_cast<__half2*>(&v2.x));
        float2 b2 = __half22float2(*reinterpret_cast<__half2*>(&v2.y));
        float2 a3 = __half22float2(*reinterpret_cast<__half2*>(&v3.x));
        float2 b3 = __half22float2(*reinterpret_cast<__half2*>(&v3.y));
        ax += w0 * a0.x + w1 * a1.x + w2 * a2.x + w3 * a3.x;
        ay += w0 * a0.y + w1 * a1.y + w2 * a2.y + w3 * a3.y;
        az += w0 * b0.x + w1 * b1.x + w2 * b2.x + w3 * b3.x;
        aw += w0 * b0.y + w1 * b1.y + w2 * b2.y + w3 * b3.y;
    }
    for (; e < t; e++) {
        int   c = __ldg(&g_col[e]);
        float w = __ldg(&g_w[e]);
        uint2 v = *(const uint2*)(yb + (size_t)c * DCAT);
        float2 f0 = __half22float2(*reinterpret_cast<__half2*>(&v.x));
        float2 f1 = __half22float2(*reinterpret_cast<__half2*>(&v.y));
        ax += w * f0.x; ay += w * f0.y; az += w * f1.x; aw += w * f1.y;
    }
    __half2 o0 = __floats2half2_rn(fmaxf(ax, 0.f), fmaxf(ay, 0.f));
    __half2 o1 = __floats2half2_rn(fmaxf(az, 0.f), fmaxf(aw, 0.f));
    uint2 o; o.x = *reinterpret_cast<uint32_t*>(&o0); o.y = *reinterpret_cast<uint32_t*>(&o1);
    *(uint2*)(g_gh + (size_t)row * DCAT + threadIdx.x * 4) = o;
}

// ---------------- GEMM2 (fp16 g input, fp16 z output) --------------------------
__global__ void __launch_bounds__(256) k_gemm2(
    const float* __restrict__ W2a, const float* __restrict__ b2a,
    const float* __restrict__ W2b, const float* __restrict__ b2b)
{
    __shared__ float sW[DCAT * 10];
    for (int i = threadIdx.x; i < DCAT * 10; i += blockDim.x) {
        int d = i / 10, c = i % 10;
        sW[i] = (d < N_HID) ? W2a[d * 10 + c] : W2b[(d - N_HID) * 10 + c];
    }
    __syncthreads();

    int lane   = threadIdx.x & 31;
    int warp   = (blockIdx.x * blockDim.x + threadIdx.x) >> 5;
    int nwarps = (gridDim.x * blockDim.x) >> 5;

    for (int row = warp; row < N_NODES; row += nwarps) {
        float acc[20];
#pragma unroll
        for (int c = 0; c < 20; c++) acc[c] = 0.f;
        const __half* grow = &g_gh[(size_t)row * DCAT];
#pragma unroll
        for (int k = 0; k < 8; k++) {
            int d0 = 64 * k + 2 * lane;
            __half2 hv = *reinterpret_cast<const __half2*>(grow + d0);
            float2 f = __half22float2(hv);
            const float* w0 = &sW[d0 * 10];
            const float* w1 = &sW[(d0 + 1) * 10];
            float* ap = (k < 4) ? acc : acc + 10;
#pragma unroll
            for (int c = 0; c < 10; c++) ap[c] += f.x * w0[c] + f.y * w1[c];
        }
#pragma unroll
        for (int c = 0; c < 20; c++) {
            float v = acc[c];
            v += __shfl_xor_sync(0xffffffffu, v, 16);
            v += __shfl_xor_sync(0xffffffffu, v, 8);
            v += __shfl_xor_sync(0xffffffffu, v, 4);
            v += __shfl_xor_sync(0xffffffffu, v, 2);
            v += __shfl_xor_sync(0xffffffffu, v, 1);
            acc[c] = v;
        }
        if (lane == 0) {
#pragma unroll
            for (int c = 0; c < 10; c++)
                g_zh[(size_t)row * 20 + c] = __float2half_rn(acc[c] + b2a[c]);
#pragma unroll
            for (int c = 0; c < 10; c++)
                g_zh[(size_t)row * 20 + 10 + c] = __float2half_rn(acc[10 + c] + b2b[c]);
        }
    }
}

// ---------------- SpMM2: 320 threads = 16 rows x 20 lanes ---------------------
__global__ void __launch_bounds__(320) k_spmm2(float* __restrict__ out) {
    int t    = threadIdx.x;
    int row  = blockIdx.x * 16 + t / 20;
    int c20  = t % 20;
    if (row >= N_NODES) return;
    int s = g_row_start[row], tend = g_row_start[row + 1];
    float acc = 0.f;
    int e = s;
    for (; e + 4 <= tend; e += 4) {
        int c0 = __ldg(&g_col[e]),     c1 = __ldg(&g_col[e + 1]);
        int c2 = __ldg(&g_col[e + 2]), c3 = __ldg(&g_col[e + 3]);
        float w0 = __ldg(&g_w[e]),     w1 = __ldg(&g_w[e + 1]);
        float w2 = __ldg(&g_w[e + 2]), w3 = __ldg(&g_w[e + 3]);
        __half z0 = g_zh[(size_t)c0 * 20 + c20];
        __half z1 = g_zh[(size_t)c1 * 20 + c20];
        __half z2 = g_zh[(size_t)c2 * 20 + c20];
        __half z3 = g_zh[(size_t)c3 * 20 + c20];
        acc += w0 * __half2float(z0) + w1 * __half2float(z1)
             + w2 * __half2float(z2) + w3 * __half2float(z3);
    }
    for (; e < tend; e++) {
        int   c = __ldg(&g_col[e]);
        float w = __ldg(&g_w[e]);
        acc += w * __half2float(g_zh[(size_t)c * 20 + c20]);
    }
    int br = c20 / 10, cc = c20 % 10;
    out[(size_t)br * (N_NODES * N_CLASS) + (size_t)row * N_CLASS + cc] = acc;
}

// ---------------- launch (fork-join: CSR chain overlaps prep+GEMM1) -----------
extern "C" void kernel_launch(void* const* d_in, const int* in_sizes, int n_in,
                              void* d_out, int out_size)
{
    const float* x   = (const float*)d_in[0];
    const int*   ei  = (const int*)d_in[1];
    const float* ew  = (const float*)d_in[2];
    const float* W1a = (const float*)d_in[3];
    const float* b1a = (const float*)d_in[4];
    const float* W2a = (const float*)d_in[5];
    const float* b2a = (const float*)d_in[6];
    const float* W1b = (const float*)d_in[7];
    const float* b1b = (const float*)d_in[8];
    const float* W2b = (const float*)d_in[9];
    const float* b2b = (const float*)d_in[10];
    float* out = (float*)d_out;

    const int SCAN_BLOCKS = (N_NODES + 255) / 256;  // 196

    // fresh fork-join resources each call (no static guards; streams/events are
    // host-side objects — no device-memory allocation)
    cudaStream_t s2;
    cudaEvent_t evFork, evJoin;
    cudaStreamCreateWithFlags(&s2, cudaStreamNonBlocking);
    cudaEventCreateWithFlags(&evFork, cudaEventDisableTiming);
    cudaEventCreateWithFlags(&evJoin, cudaEventDisableTiming);

    // fork: CSR chain on s2
    cudaEventRecord(evFork, 0);
    cudaStreamWaitEvent(s2, evFork, 0);
    k_detect<<<1, 32, 0, s2>>>(ei);
    k_zero<<<(N_NODES + 255) / 256, 256, 0, s2>>>();
    k_hist<<<(N_EDGES + 255) / 256, 256, 0, s2>>>(ei);
    k_scan1<<<SCAN_BLOCKS, 256, 0, s2>>>();
    k_scan2<<<1, 256, 0, s2>>>(SCAN_BLOCKS);
    k_scan3<<<SCAN_BLOCKS, 256, 0, s2>>>();
    k_scatter<<<(N_EDGES + 255) / 256, 256, 0, s2>>>(ei, ew);
    cudaEventRecord(evJoin, s2);

    // main stream: prep + GEMM1 (independent of CSR)
    k_prep_x<<<(MPAD * 128 + 255) / 256, 256>>>(x);
    k_prep_w<<<(DCAT * KPAD + 255) / 256, 256>>>(W1a, b1a, W1b, b1b);
    k_gemm1_mma<<<dim3(DCAT / BN, MPAD / BM), 256>>>();

    // join: SpMM needs both CSR and y
    cudaStreamWaitEvent(0, evJoin, 0);
    k_spmm1<<<N_NODES, 128>>>();
    k_gemm2<<<782, 256>>>(W2a, b2a, W2b, b2b);
    k_spmm2<<<(N_NODES + 15) / 16, 320>>>(out);
}

// round 16
// speedup vs baseline: 1.1353x; 1.0876x over previous
#include <cuda_runtime.h>
#include <cuda_fp16.h>
#include <cstdint>

#define N_NODES 50000
#define N_EDGES 800000
#define N_FEAT  500
#define N_HID   256
#define DCAT    512   // fused hidden width (2 branches x 256)
#define N_CLASS 10
#define MPAD    50048 // 391 * 128
#define KPAD    512

// ---------------- device scratch ----------------------------------------------
__device__ int   g_is64;
__device__ int   g_counts[N_NODES];
__device__ int   g_row_start[N_NODES + 1];
__device__ int   g_cursor[N_NODES];
__device__ int   g_blockSums[256];
__device__ int   g_blockOffs[256];
__device__ int   g_col[N_EDGES];
__device__ float g_w[N_EDGES];
__device__ __align__(16) __half g_xh[(size_t)MPAD * KPAD];   // fp16(x)
__device__ __align__(16) __half g_whT[DCAT * KPAD];          // [n][k] fp16(w)
__device__ float g_bcat[DCAT];
__device__ __align__(16) __half g_yh[(size_t)MPAD * DCAT];   // y in fp16
__device__ __align__(16) __half g_gh[(size_t)N_NODES * DCAT];// relu(spmm(y)) fp16
__device__ __half g_zh[(size_t)N_NODES * 20];                // z in fp16

#define CP_ASYNC16(dst, src) \
    asm volatile("cp.async.cg.shared.global [%0], [%1], 16;" :: "r"(dst), "l"(src))
#define CP_COMMIT() asm volatile("cp.async.commit_group;" ::: "memory")
#define CP_WAIT0()  asm volatile("cp.async.wait_group 0;" ::: "memory")
#define CP_WAIT1()  asm volatile("cp.async.wait_group 1;" ::: "memory")

#define LDSM_X4(r0, r1, r2, r3, addr) \
    asm volatile("ldmatrix.sync.aligned.m8n8.x4.shared.b16 {%0,%1,%2,%3}, [%4];" \
                 : "=r"(r0), "=r"(r1), "=r"(r2), "=r"(r3) : "r"(addr))

__device__ __forceinline__ uint32_t smem_u32(const void* p) {
    uint32_t a;
    asm("{ .reg .u64 t; cvta.to.shared.u64 t, %1; cvt.u32.u64 %0, t; }" : "=r"(a) : "l"(p));
    return a;
}

// ---------------- dtype detect ------------------------------------------------
__global__ void k_detect(const int* __restrict__ ei32) {
    if (threadIdx.x == 0) {
        int odd_nonzero = 0;
        for (int i = 0; i < 64; i++) odd_nonzero |= ei32[2 * i + 1];
        g_is64 = (odd_nonzero == 0) ? 1 : 0;
    }
}
__device__ __forceinline__ int edge_row(const int* ei32, int e, int is64) {
    return is64 ? ei32[2 * e] : ei32[e];
}
__device__ __forceinline__ int edge_col(const int* ei32, int e, int is64) {
    return is64 ? ei32[2 * (N_EDGES + e)] : ei32[N_EDGES + e];
}

// ---------------- CSR build ---------------------------------------------------
__global__ void k_zero() {
    int i = blockIdx.x * blockDim.x + threadIdx.x;
    if (i < N_NODES) { g_counts[i] = 0; g_cursor[i] = 0; }
}
__global__ void k_hist(const int* __restrict__ ei32) {
    int e = blockIdx.x * blockDim.x + threadIdx.x;
    if (e < N_EDGES) {
        int r = edge_row(ei32, e, g_is64);
        if ((unsigned)r < N_NODES) atomicAdd(&g_counts[r], 1);
    }
}
__global__ void k_scan1() {
    __shared__ int sm[256];
    int i = blockIdx.x * 256 + threadIdx.x;
    sm[threadIdx.x] = (i < N_NODES) ? g_counts[i] : 0;
    __syncthreads();
    for (int off = 128; off; off >>= 1) {
        if (threadIdx.x < off) sm[threadIdx.x] += sm[threadIdx.x + off];
        __syncthreads();
    }
    if (threadIdx.x == 0) g_blockSums[blockIdx.x] = sm[0];
}
__global__ void k_scan2(int nblocks) {
    __shared__ int sm[256];
    int v = (threadIdx.x < nblocks) ? g_blockSums[threadIdx.x] : 0;
    sm[threadIdx.x] = v;
    __syncthreads();
    for (int off = 1; off < 256; off <<= 1) {
        int t = (threadIdx.x >= off) ? sm[threadIdx.x - off] : 0;
        __syncthreads();
        sm[threadIdx.x] += t;
        __syncthreads();
    }
    if (threadIdx.x < nblocks) g_blockOffs[threadIdx.x] = sm[threadIdx.x] - v;
    if (threadIdx.x == 255) g_row_start[N_NODES] = sm[255];
}
__global__ void k_scan3() {
    __shared__ int sm[256];
    int i = blockIdx.x * 256 + threadIdx.x;
    int v = (i < N_NODES) ? g_counts[i] : 0;
    sm[threadIdx.x] = v;
    __syncthreads();
    for (int off = 1; off < 256; off <<= 1) {
        int t = (threadIdx.x >= off) ? sm[threadIdx.x - off] : 0;
        __syncthreads();
        sm[threadIdx.x] += t;
        __syncthreads();
    }
    if (i < N_NODES) g_row_start[i] = g_blockOffs[blockIdx.x] + sm[threadIdx.x] - v;
}
__global__ void k_scatter(const int* __restrict__ ei32, const float* __restrict__ ew) {
    int e = blockIdx.x * blockDim.x + threadIdx.x;
    if (e < N_EDGES) {
        int is64 = g_is64;
        int r = edge_row(ei32, e, is64);
        int c = edge_col(ei32, e, is64);
        if ((unsigned)r < N_NODES && (unsigned)c < N_NODES) {
            int p = g_row_start[r] + atomicAdd(&g_cursor[r], 1);
            g_col[p] = c;
            g_w[p]   = ew[e];
        }
    }
}

// ---------------- prep: x -> fp16, w -> fp16 -----------------------------------
__global__ void k_prep_x(const float* __restrict__ x) {
    int t  = blockIdx.x * 256 + threadIdx.x;
    int r  = t >> 7;
    int c0 = (t & 127) * 4;
    if (r >= MPAD) return;
    float4 v = make_float4(0.f, 0.f, 0.f, 0.f);
    if (r < N_NODES && c0 < N_FEAT)
        v = *(const float4*)(x + (size_t)r * N_FEAT + c0);
    __half h[4];
    h[0] = __float2half_rn(v.x); h[1] = __float2half_rn(v.y);
    h[2] = __float2half_rn(v.z); h[3] = __float2half_rn(v.w);
    *(uint2*)(g_xh + (size_t)r * KPAD + c0) = *(uint2*)h;
}
__global__ void k_prep_w(const float* __restrict__ W1a, const float* __restrict__ b1a,
                         const float* __restrict__ W1b, const float* __restrict__ b1b) {
    int t = blockIdx.x * 256 + threadIdx.x;
    if (t >= DCAT * KPAD) return;
    int n = t >> 9, k = t & 511;
    float v = 0.f;
    if (k < N_FEAT)
        v = (n < N_HID) ? W1a[k * N_HID + n] : W1b[k * N_HID + (n - N_HID)];
    g_whT[n * KPAD + k] = __float2half_rn(v);
    if (t < DCAT) g_bcat[t] = (t < N_HID) ? b1a[t] : b1b[t - N_HID];
}

// ---------------- GEMM1 (fp16, ldmatrix frags, 3-stage cp.async) --------------
#define BM 128
#define BN 128
#define BK 16
#define PITCH 24
#define NSTAGE (KPAD / BK)  // 32

__device__ __forceinline__ void mma16816(float* c, const unsigned* a, const unsigned* b) {
    asm volatile(
        "mma.sync.aligned.m16n8k16.row.col.f32.f16.f16.f32 "
        "{%0,%1,%2,%3}, {%4,%5,%6,%7}, {%8,%9}, {%0,%1,%2,%3};\n"
        : "+f"(c[0]), "+f"(c[1]), "+f"(c[2]), "+f"(c[3])
        : "r"(a[0]), "r"(a[1]), "r"(a[2]), "r"(a[3]), "r"(b[0]), "r"(b[1]));
}

__global__ void __launch_bounds__(256, 2) k_gemm1_mma() {
    __shared__ __align__(16) __half sAh[3][BM * PITCH];
    __shared__ __align__(16) __half sBh[3][BN * PITCH];

    const int tid  = threadIdx.x;
    const int bm   = blockIdx.y * BM;
    const int bn   = blockIdx.x * BN;
    const int wid  = tid >> 5, lane = tid & 31;
    const int wm   = wid & 1, wn = wid >> 1;
    const int mw   = wm * 64, nw = wn * 32;
    const int gid  = lane >> 2;
    const int tk4  = lane & 3;

    // loader mapping: 256 threads, each one 16B cp.async per matrix per stage
    const int lr = tid >> 1;
    const int lk = (tid & 1) * 8;
    const size_t aoff = (size_t)(bm + lr) * KPAD + lk;
    const size_t boff = (size_t)(bn + lr) * KPAD + lk;
    const uint32_t sAh0 = smem_u32(&sAh[0][0]);
    const uint32_t sBh0 = smem_u32(&sBh[0][0]);
    const uint32_t soffB = (lr * PITCH + lk) * 2;   // byte offset within a stage
    const uint32_t stageB = BM * PITCH * 2;         // bytes per stage (A == B size)

    // ldmatrix per-lane base offsets (bytes, within a stage)
    // A: mats {rows m..m+7 k0-7, m+8..15 k0-7, m..7 k8-15, m+8..15 k8-15}
    const uint32_t aLdsm = ((uint32_t)(mw + (lane & 7) + ((lane >> 3) & 1) * 8) * PITCH
                            + ((lane >> 4) & 1) * 8) * 2;
    // B: mats {rows n..n+7 k0-7, n..7 k8-15, n+8..15 k0-7, n+8..15 k8-15}
    const uint32_t bLdsm = ((uint32_t)(nw + (lane & 7) + ((lane >> 4) & 1) * 8) * PITCH
                            + ((lane >> 3) & 1) * 8) * 2;

    float acc[16][4];
#pragma unroll
    for (int i = 0; i < 16; i++)
#pragma unroll
        for (int j = 0; j < 4; j++) acc[i][j] = 0.f;

    // prologue: stages 0 and 1 in flight
    CP_ASYNC16(sAh0 + soffB, g_xh + aoff);
    CP_ASYNC16(sBh0 + soffB, g_whT + boff);
    CP_COMMIT();
    CP_ASYNC16(sAh0 + stageB + soffB, g_xh + aoff + BK);
    CP_ASYNC16(sBh0 + stageB + soffB, g_whT + boff + BK);
    CP_COMMIT();
    CP_WAIT1();          // stage 0 complete
    __syncthreads();

    for (int s = 0; s < NSTAGE; s++) {
        const int buf = s % 3;
        if (s + 2 < NSTAGE) {
            const int nbuf = (s + 2) % 3;
            int k0 = (s + 2) * BK;
            CP_ASYNC16(sAh0 + nbuf * stageB + soffB, g_xh + aoff + k0);
            CP_ASYNC16(sBh0 + nbuf * stageB + soffB, g_whT + boff + k0);
            CP_COMMIT();
        }

        // fragment loads via ldmatrix.x4
        unsigned Ah[4][4], Bh[4][2];
        {
            uint32_t ab = sAh0 + buf * stageB + aLdsm;
            uint32_t bb = sBh0 + buf * stageB + bLdsm;
            LDSM_X4(Ah[0][0], Ah[0][1], Ah[0][2], Ah[0][3], ab);
            LDSM_X4(Ah[1][0], Ah[1][1], Ah[1][2], Ah[1][3], ab + 16 * PITCH * 2);
            LDSM_X4(Ah[2][0], Ah[2][1], Ah[2][2], Ah[2][3], ab + 32 * PITCH * 2);
            LDSM_X4(Ah[3][0], Ah[3][1], Ah[3][2], Ah[3][3], ab + 48 * PITCH * 2);
            LDSM_X4(Bh[0][0], Bh[0][1], Bh[1][0], Bh[1][1], bb);
            LDSM_X4(Bh[2][0], Bh[2][1], Bh[3][0], Bh[3][1], bb + 16 * PITCH * 2);
        }
#pragma unroll
        for (int mi = 0; mi < 4; mi++)
#pragma unroll
            for (int ni = 0; ni < 4; ni++)
                mma16816(acc[mi * 4 + ni], Ah[mi], Bh[ni]);

        if (s + 1 < NSTAGE) {
            if (s + 2 < NSTAGE) CP_WAIT1(); else CP_WAIT0();
            __syncthreads();
        }
    }

    // epilogue: bias add in fp32, store fp16
#pragma unroll
    for (int mi = 0; mi < 4; mi++) {
#pragma unroll
        for (int ni = 0; ni < 4; ni++) {
            int r = bm + mw + mi * 16 + gid;
            int c = bn + nw + ni * 8 + tk4 * 2;
            float b0 = g_bcat[c], b1 = g_bcat[c + 1];
            float* acc4 = acc[mi * 4 + ni];
            __half2 h0 = __floats2half2_rn(acc4[0] + b0, acc4[1] + b1);
            __half2 h1 = __floats2half2_rn(acc4[2] + b0, acc4[3] + b1);
            *reinterpret_cast<__half2*>(&g_yh[(size_t)r * DCAT + c]) = h0;
            *reinterpret_cast<__half2*>(&g_yh[(size_t)(r + 8) * DCAT + c]) = h1;
        }
    }
}

// ---------------- SpMM1: gh[row] = relu( sum_e w * yh[col] ), D=512 -----------
__global__ void __launch_bounds__(128) k_spmm1() {
    int row = blockIdx.x;
    int s = g_row_start[row], t = g_row_start[row + 1];
    const __half* yb = g_yh + threadIdx.x * 4;
    float ax = 0.f, ay = 0.f, az = 0.f, aw = 0.f;
    int e = s;
    for (; e + 4 <= t; e += 4) {
        int c0 = __ldg(&g_col[e]),     c1 = __ldg(&g_col[e + 1]);
        int c2 = __ldg(&g_col[e + 2]), c3 = __ldg(&g_col[e + 3]);
        float w0 = __ldg(&g_w[e]),     w1 = __ldg(&g_w[e + 1]);
        float w2 = __ldg(&g_w[e + 2]), w3 = __ldg(&g_w[e + 3]);
        uint2 v0 = *(const uint2*)(yb + (size_t)c0 * DCAT);
        uint2 v1 = *(const uint2*)(yb + (size_t)c1 * DCAT);
        uint2 v2 = *(const uint2*)(yb + (size_t)c2 * DCAT);
        uint2 v3 = *(const uint2*)(yb + (size_t)c3 * DCAT);
        float2 a0 = __half22float2(*reinterpret_cast<__half2*>(&v0.x));
        float2 b0 = __half22float2(*reinterpret_cast<__half2*>(&v0.y));
        float2 a1 = __half22float2(*reinterpret_cast<__half2*>(&v1.x));
        float2 b1 = __half22float2(*reinterpret_cast<__half2*>(&v1.y));
        float2 a2 = __half22float2(*reinterpret_cast<__half2*>(&v2.x));
        float2 b2 = __half22float2(*reinterpret_cast<__half2*>(&v2.y));
        float2 a3 = __half22float2(*reinterpret_cast<__half2*>(&v3.x));
        float2 b3 = __half22float2(*reinterpret_cast<__half2*>(&v3.y));
        ax += w0 * a0.x + w1 * a1.x + w2 * a2.x + w3 * a3.x;
        ay += w0 * a0.y + w1 * a1.y + w2 * a2.y + w3 * a3.y;
        az += w0 * b0.x + w1 * b1.x + w2 * b2.x + w3 * b3.x;
        aw += w0 * b0.y + w1 * b1.y + w2 * b2.y + w3 * b3.y;
    }
    for (; e < t; e++) {
        int   c = __ldg(&g_col[e]);
        float w = __ldg(&g_w[e]);
        uint2 v = *(const uint2*)(yb + (size_t)c * DCAT);
        float2 f0 = __half22float2(*reinterpret_cast<__half2*>(&v.x));
        float2 f1 = __half22float2(*reinterpret_cast<__half2*>(&v.y));
        ax += w * f0.x; ay += w * f0.y; az += w * f1.x; aw += w * f1.y;
    }
    __half2 o0 = __floats2half2_rn(fmaxf(ax, 0.f), fmaxf(ay, 0.f));
    __half2 o1 = __floats2half2_rn(fmaxf(az, 0.f), fmaxf(aw, 0.f));
    uint2 o; o.x = *reinterpret_cast<uint32_t*>(&o0); o.y = *reinterpret_cast<uint32_t*>(&o1);
    *(uint2*)(g_gh + (size_t)row * DCAT + threadIdx.x * 4) = o;
}

// ---------------- GEMM2 (fp16 g input, fp16 z output) --------------------------
__global__ void __launch_bounds__(256) k_gemm2(
    const float* __restrict__ W2a, const float* __restrict__ b2a,
    const float* __restrict__ W2b, const float* __restrict__ b2b)
{
    __shared__ float sW[DCAT * 10];
    for (int i = threadIdx.x; i < DCAT * 10; i += blockDim.x) {
        int d = i / 10, c = i % 10;
        sW[i] = (d < N_HID) ? W2a[d * 10 + c] : W2b[(d - N_HID) * 10 + c];
    }
    __syncthreads();

    int lane   = threadIdx.x & 31;
    int warp   = (blockIdx.x * blockDim.x + threadIdx.x) >> 5;
    int nwarps = (gridDim.x * blockDim.x) >> 5;

    for (int row = warp; row < N_NODES; row += nwarps) {
        float acc[20];
#pragma unroll
        for (int c = 0; c < 20; c++) acc[c] = 0.f;
        const __half* grow = &g_gh[(size_t)row * DCAT];
#pragma unroll
        for (int k = 0; k < 8; k++) {
            int d0 = 64 * k + 2 * lane;
            __half2 hv = *reinterpret_cast<const __half2*>(grow + d0);
            float2 f = __half22float2(hv);
            const float* w0 = &sW[d0 * 10];
            const float* w1 = &sW[(d0 + 1) * 10];
            float* ap = (k < 4) ? acc : acc + 10;
#pragma unroll
            for (int c = 0; c < 10; c++) ap[c] += f.x * w0[c] + f.y * w1[c];
        }
#pragma unroll
        for (int c = 0; c < 20; c++) {
            float v = acc[c];
            v += __shfl_xor_sync(0xffffffffu, v, 16);
            v += __shfl_xor_sync(0xffffffffu, v, 8);
            v += __shfl_xor_sync(0xffffffffu, v, 4);
            v += __shfl_xor_sync(0xffffffffu, v, 2);
            v += __shfl_xor_sync(0xffffffffu, v, 1);
            acc[c] = v;
        }
        if (lane == 0) {
#pragma unroll
            for (int c = 0; c < 10; c++)
                g_zh[(size_t)row * 20 + c] = __float2half_rn(acc[c] + b2a[c]);
#pragma unroll
            for (int c = 0; c < 10; c++)
                g_zh[(size_t)row * 20 + 10 + c] = __float2half_rn(acc[10 + c] + b2b[c]);
        }
    }
}

// ---------------- SpMM2: 320 threads = 16 rows x 20 lanes ---------------------
__global__ void __launch_bounds__(320) k_spmm2(float* __restrict__ out) {
    int t    = threadIdx.x;
    int row  = blockIdx.x * 16 + t / 20;
    int c20  = t % 20;
    if (row >= N_NODES) return;
    int s = g_row_start[row], tend = g_row_start[row + 1];
    float acc = 0.f;
    int e = s;
    for (; e + 4 <= tend; e += 4) {
        int c0 = __ldg(&g_col[e]),     c1 = __ldg(&g_col[e + 1]);
        int c2 = __ldg(&g_col[e + 2]), c3 = __ldg(&g_col[e + 3]);
        float w0 = __ldg(&g_w[e]),     w1 = __ldg(&g_w[e + 1]);
        float w2 = __ldg(&g_w[e + 2]), w3 = __ldg(&g_w[e + 3]);
        __half z0 = g_zh[(size_t)c0 * 20 + c20];
        __half z1 = g_zh[(size_t)c1 * 20 + c20];
        __half z2 = g_zh[(size_t)c2 * 20 + c20];
        __half z3 = g_zh[(size_t)c3 * 20 + c20];
        acc += w0 * __half2float(z0) + w1 * __half2float(z1)
             + w2 * __half2float(z2) + w3 * __half2float(z3);
    }
    for (; e < tend; e++) {
        int   c = __ldg(&g_col[e]);
        float w = __ldg(&g_w[e]);
        acc += w * __half2float(g_zh[(size_t)c * 20 + c20]);
    }
    int br = c20 / 10, cc = c20 % 10;
    out[(size_t)br * (N_NODES * N_CLASS) + (size_t)row * N_CLASS + cc] = acc;
}

// ---------------- launch (fork-join: CSR chain overlaps prep+GEMM1) -----------
extern "C" void kernel_launch(void* const* d_in, const int* in_sizes, int n_in,
                              void* d_out, int out_size)
{
    const float* x   = (const float*)d_in[0];
    const int*   ei  = (const int*)d_in[1];
    const float* ew  = (const float*)d_in[2];
    const float* W1a = (const float*)d_in[3];
    const float* b1a = (const float*)d_in[4];
    const float* W2a = (const float*)d_in[5];
    const float* b2a = (const float*)d_in[6];
    const float* W1b = (const float*)d_in[7];
    const float* b1b = (const float*)d_in[8];
    const float* W2b = (const float*)d_in[9];
    const float* b2b = (const float*)d_in[10];
    float* out = (float*)d_out;

    const int SCAN_BLOCKS = (N_NODES + 255) / 256;  // 196

    cudaStream_t s2;
    cudaEvent_t evFork, evJoin;
    cudaStreamCreateWithFlags(&s2, cudaStreamNonBlocking);
    cudaEventCreateWithFlags(&evFork, cudaEventDisableTiming);
    cudaEventCreateWithFlags(&evJoin, cudaEventDisableTiming);

    // fork: CSR chain on s2
    cudaEventRecord(evFork, 0);
    cudaStreamWaitEvent(s2, evFork, 0);
    k_detect<<<1, 32, 0, s2>>>(ei);
    k_zero<<<(N_NODES + 255) / 256, 256, 0, s2>>>();
    k_hist<<<(N_EDGES + 255) / 256, 256, 0, s2>>>(ei);
    k_scan1<<<SCAN_BLOCKS, 256, 0, s2>>>();
    k_scan2<<<1, 256, 0, s2>>>(SCAN_BLOCKS);
    k_scan3<<<SCAN_BLOCKS, 256, 0, s2>>>();
    k_scatter<<<(N_EDGES + 255) / 256, 256, 0, s2>>>(ei, ew);
    cudaEventRecord(evJoin, s2);

    // main stream: prep + GEMM1
    k_prep_x<<<(MPAD * 128 + 255) / 256, 256>>>(x);
    k_prep_w<<<(DCAT * KPAD + 255) / 256, 256>>>(W1a, b1a, W1b, b1b);
    k_gemm1_mma<<<dim3(DCAT / BN, MPAD / BM), 256>>>();

    // join: SpMM needs both CSR and y
    cudaStreamWaitEvent(0, evJoin, 0);
    k_spmm1<<<N_NODES, 128>>>();
    k_gemm2<<<782, 256>>>(W2a, b2a, W2b, b2b);
    k_spmm2<<<(N_NODES + 15) / 16, 320>>>(out);
}